// round 12
// baseline (speedup 1.0000x reference)
#include <cuda_runtime.h>
#include <math.h>

#define Bn 256
#define Fn 200
#define E1n 64
#define E2n 128
#define Hn 4
#define ALPHAc 0.2f
#define NEGc -9000000000000000.0f

#define APW 68                    // attnT row width (tile rows <=64 + pad)
#define BUFSZ (Fn*APW)            // 13600 floats per prob buffer

typedef unsigned long long ull;

// ---- packed f32x2 helpers ----
__device__ __forceinline__ ull dup2(float v) {
    ull r; asm("mov.b64 %0, {%1, %1};" : "=l"(r) : "f"(v)); return r;
}
__device__ __forceinline__ void fma2(ull &d, ull a, ull b) {
    asm("fma.rn.f32x2 %0, %1, %2, %0;" : "+l"(d) : "l"(a), "l"(b));
}
__device__ __forceinline__ void add2(ull &d, ull a) {
    asm("add.rn.f32x2 %0, %0, %1;" : "+l"(d) : "l"(a));
}
__device__ __forceinline__ float2 unpk(ull v) {
    float2 r; asm("mov.b64 {%0, %1}, %2;" : "=f"(r.x), "=f"(r.y) : "l"(v)); return r;
}
__device__ __forceinline__ ull d2l(double d) { return __double_as_longlong(d); }

// row-pair-packed step: acc[rp*4+c] = (out[2rp], out[2rp+1]) at col c.
// PA = pairs (0,1),(2,3) as double2; PB = pairs (4,5),(6,7); HV = 4 h cols.
// 4 dups + 16 fma2 per y.
#define STEP8(PA, PB, HV)                                                  \
    {                                                                      \
        ull pa0 = d2l(PA.x), pa1 = d2l(PA.y), pb0 = d2l(PB.x), pb1 = d2l(PB.y); \
        ull q;                                                             \
        q = dup2(HV.x); fma2(acc[0], pa0, q); fma2(acc[4], pa1, q); fma2(acc[8],  pb0, q); fma2(acc[12], pb1, q); \
        q = dup2(HV.y); fma2(acc[1], pa0, q); fma2(acc[5], pa1, q); fma2(acc[9],  pb0, q); fma2(acc[13], pb1, q); \
        q = dup2(HV.z); fma2(acc[2], pa0, q); fma2(acc[6], pa1, q); fma2(acc[10], pb0, q); fma2(acc[14], pb1, q); \
        q = dup2(HV.w); fma2(acc[3], pa0, q); fma2(acc[7], pa1, q); fma2(acc[11], pb0, q); fma2(acc[15], pb1, q); \
    }

// ---------------------------------------------------------------------------
// Fused GAT kernel, CTA per (h, b):
//   proj -> si/sj -> { prefetch(t+1) ; GEMM(t) ; score(t+1) } over 4 tiles.
// ---------------------------------------------------------------------------
__global__ __launch_bounds__(512) void k_fused(const float* __restrict__ x,
                                               const float* __restrict__ adj,
                                               const float* __restrict__ W,
                                               const float* __restrict__ a,
                                               float* __restrict__ out) {
    extern __shared__ float smem[];
    float* hs   = smem;                     // 25600
    float* bufs = smem + Fn*E2n;            // 2 * 13600
    float* sjs  = bufs + 2*BUFSZ;           // 200
    float* sis  = sjs + Fn;                 // 200
    float* rsc  = sis + Fn;                 // 2 * 64
    float* xs   = bufs;                     // alias (13000 floats, proj only)
    float* ws   = bufs + 13000;             // alias (8192 floats, proj only)

    int h = blockIdx.x, b = blockIdx.y;
    int tid = threadIdx.x;
    int warp = tid >> 5, lane = tid & 31;

    // ---- stage xs (padded 65) and ws ----
    const float4* xg = (const float4*)(x + (size_t)b * Fn * E1n);
    for (int i = tid; i < Fn*E1n/4; i += 512) {
        float4 v = xg[i];
        int r = i >> 4, c = (i & 15) << 2;
        float* p = &xs[r*65 + c];
        p[0] = v.x; p[1] = v.y; p[2] = v.z; p[3] = v.w;
    }
    const float4* wg = (const float4*)(W + (size_t)h * E1n * E2n);
    float4* ws4 = (float4*)ws;
    for (int i = tid; i < E1n*E2n/4; i += 512) ws4[i] = wg[i];
    __syncthreads();

    // ---- proj GEMM hs = xs @ ws (split-column mapping) ----
    {
        int tr = tid >> 4;        // 0..31; active tr<25
        int tc = tid & 15;
        if (tr < 25) {
            ull acc[32];
            #pragma unroll
            for (int i = 0; i < 32; ++i) acc[i] = 0ull;

            #pragma unroll 2
            for (int k = 0; k < E1n; ++k) {
                double2 w0 = *(const double2*)&ws[k*E2n + tc*4];
                double2 w1 = *(const double2*)&ws[k*E2n + 64 + tc*4];
                ull wv0 = d2l(w0.x), wv1 = d2l(w0.y), wv2 = d2l(w1.x), wv3 = d2l(w1.y);
                ull q;
                #pragma unroll
                for (int r = 0; r < 8; ++r) {
                    q = dup2(xs[(tr*8 + r)*65 + k]);
                    fma2(acc[r*4+0], q, wv0);
                    fma2(acc[r*4+1], q, wv1);
                    fma2(acc[r*4+2], q, wv2);
                    fma2(acc[r*4+3], q, wv3);
                }
            }
            #pragma unroll
            for (int r = 0; r < 8; ++r) {
                float2 v0 = unpk(acc[r*4+0]);
                float2 v1 = unpk(acc[r*4+1]);
                float2 v2 = unpk(acc[r*4+2]);
                float2 v3 = unpk(acc[r*4+3]);
                float* dp = &hs[(size_t)(tr*8 + r)*E2n + tc*4];
                *(float4*)dp        = make_float4(v0.x, v0.y, v1.x, v1.y);
                *(float4*)(dp + 64) = make_float4(v2.x, v2.y, v3.x, v3.y);
            }
        }
    }
    __syncthreads();     // hs complete; xs/ws dead

    // ---- si/sj (warp per row) ----
    {
        const float* ap = a + (size_t)h * 2 * E2n;
        float4 aiv = *(const float4*)&ap[lane*4];
        float4 ajv = *(const float4*)&ap[E2n + lane*4];
        #pragma unroll 1
        for (int it = 0; it < 13; ++it) {
            int f = it*16 + warp;
            if (f < Fn) {
                float4 hv = *(const float4*)&hs[(size_t)f*E2n + lane*4];
                float pi = hv.x*aiv.x + hv.y*aiv.y + hv.z*aiv.z + hv.w*aiv.w;
                float pj = hv.x*ajv.x + hv.y*ajv.y + hv.z*ajv.z + hv.w*ajv.w;
                #pragma unroll
                for (int o = 16; o > 0; o >>= 1) {
                    pi += __shfl_xor_sync(0xffffffffu, pi, o);
                    pj += __shfl_xor_sync(0xffffffffu, pj, o);
                }
                if (lane == 0) { sis[f] = pi; sjs[f] = pj; }
            }
        }
    }
    __syncthreads();     // sis/sjs visible

    int grp = tid >> 8;           // split-K: 0 -> y [0,100), 1 -> y [100,200)
    int gt  = tid & 255;
    int gtr = gt >> 5;            // 0..7 row-group (rows gtr*8..+7)
    int y0  = grp * 100;

    float m[4][7];   // prefetched adj rows: [pair*2+half][j]

    // ---- prefetch adj rows for tile [st0, st0+svalid) into registers ----
    auto prefetch = [&](int st0, int svalid) {
        #pragma unroll
        for (int p = 0; p < 2; ++p)
            #pragma unroll
            for (int hf = 0; hf < 2; ++hf) {
                int rt = p*32 + warp + hf*16;
                if (rt < svalid) {
                    const float* rp = adj + (size_t)(st0 + rt) * Fn;
                    #pragma unroll
                    for (int j = 0; j < 7; ++j) {
                        int y = j*32 + lane;
                        m[p*2+hf][j] = (y < Fn) ? rp[y] : 0.f;
                    }
                }
            }
    };

    // ---- score from prefetched m: probs into bufW, 1/sum into rscW ----
    auto score_compute = [&](float* bufW, float* rscW, int st0, int svalid) {
        #pragma unroll 1
        for (int p = 0; p < 2; ++p) {
            int rt0 = p*32 + warp;
            int rt1 = rt0 + 16;
            bool v0 = rt0 < svalid, v1 = rt1 < svalid;   // warp-uniform
            if (!v0) continue;

            float si0 = sis[st0 + rt0];
            float si1 = v1 ? sis[st0 + rt1] : 0.f;

            float s0[7], s1[7];
            #pragma unroll
            for (int j = 0; j < 7; ++j) {
                int y = j*32 + lane;
                if (y < Fn) {
                    float sjv = sjs[y];
                    float z0 = si0 + sjv;
                    float e0 = (z0 > 0.f) ? z0 : ALPHAc * z0;
                    float m0 = m[p*2][j];
                    s0[j] = e0 * ((m0 > 0.f) ? m0 : NEGc);
                    if (v1) {
                        float z1 = si1 + sjv;
                        float e1 = (z1 > 0.f) ? z1 : ALPHAc * z1;
                        float m1 = m[p*2+1][j];
                        s1[j] = e1 * ((m1 > 0.f) ? m1 : NEGc);
                    } else s1[j] = -INFINITY;
                } else { s0[j] = -INFINITY; s1[j] = -INFINITY; }
            }

            float mx0 = s0[0], mx1 = s1[0];
            #pragma unroll
            for (int j = 1; j < 7; ++j) { mx0 = fmaxf(mx0, s0[j]); mx1 = fmaxf(mx1, s1[j]); }
            #pragma unroll
            for (int o = 16; o > 0; o >>= 1) {
                mx0 = fmaxf(mx0, __shfl_xor_sync(0xffffffffu, mx0, o));
                mx1 = fmaxf(mx1, __shfl_xor_sync(0xffffffffu, mx1, o));
            }
            float p0[7], p1[7], sum0 = 0.f, sum1 = 0.f;
            #pragma unroll
            for (int j = 0; j < 7; ++j) {
                p0[j] = __expf(s0[j] - mx0); sum0 += p0[j];
                p1[j] = __expf(s1[j] - mx1); sum1 += p1[j];
            }
            #pragma unroll
            for (int o = 16; o > 0; o >>= 1) {
                sum0 += __shfl_xor_sync(0xffffffffu, sum0, o);
                sum1 += __shfl_xor_sync(0xffffffffu, sum1, o);
            }
            #pragma unroll
            for (int j = 0; j < 7; ++j) {
                int y = j*32 + lane;
                if (y < Fn) {
                    bufW[y*APW + rt0] = p0[j];
                    if (v1) bufW[y*APW + rt1] = p1[j];
                }
            }
            if (lane == 0) {
                rscW[rt0] = 1.f / sum0;
                if (v1) rscW[rt1] = 1.f / sum1;
            }
        }
    };

    // ---- prologue: tile 0 probs ----
    prefetch(0, 64);
    score_compute(bufs, rsc, 0, 64);
    __syncthreads();

    #pragma unroll 1
    for (int t = 0; t < 4; ++t) {
        int t0 = t*64;
        int valid = (t < 3) ? 64 : 8;
        int nvalid = (t+1 < 3) ? 64 : 8;
        float* bufR = bufs + (t&1)*BUFSZ;
        float* rscR = rsc + (t&1)*64;
        bool on = (gtr*8 < valid);

        if (t < 3) prefetch((t+1)*64, nvalid);   // 28 LDGs in flight over GEMM

        ull acc[16];
        #pragma unroll
        for (int i = 0; i < 16; ++i) acc[i] = 0ull;

        if (on) {
            const float* pA = bufR + (size_t)y0*APW + gtr*8;
            const float* pH = hs + (size_t)y0*E2n + lane*4;

            double2 aA0 = *(const double2*)&pA[0];
            double2 aA1 = *(const double2*)&pA[4];
            float4  hA  = *(const float4*)&pH[0];

            // over-reads at the last step land in in-bounds dead smem.
            #pragma unroll 1
            for (int y = 0; y < 100; y += 2) {
                double2 aB0 = *(const double2*)&pA[(y+1)*APW];
                double2 aB1 = *(const double2*)&pA[(y+1)*APW + 4];
                float4  hB  = *(const float4*)&pH[(y+1)*E2n];
                STEP8(aA0, aA1, hA);
                aA0 = *(const double2*)&pA[(y+2)*APW];
                aA1 = *(const double2*)&pA[(y+2)*APW + 4];
                hA  = *(const float4*)&pH[(y+2)*E2n];
                STEP8(aB0, aB1, hB);
            }
        }

        // overlapped: next tile's probs from prefetched registers
        if (t < 3) score_compute(bufs + ((t+1)&1)*BUFSZ, rsc + ((t+1)&1)*64,
                                 (t+1)*64, nvalid);
        __syncthreads();    // GEMM reads of bufR done + next probs complete

        // group B parks partials (conflict-free ull layout in consumed buffer)
        ull* red = (ull*)bufR;
        if (grp == 1 && on) {
            #pragma unroll
            for (int i = 0; i < 16; ++i) red[i*256 + gt] = acc[i];
        }
        __syncthreads();    // partials visible

        // group A: add partials, scale (per-row pair), store
        if (grp == 0 && on) {
            #pragma unroll
            for (int i = 0; i < 16; ++i) add2(acc[i], red[i*256 + gt]);
            #pragma unroll
            for (int rp = 0; rp < 4; ++rp) {
                int r0 = gtr*8 + rp*2;
                float2 sc = *(const float2*)&rscR[r0];
                float2 v0 = unpk(acc[rp*4+0]);
                float2 v1 = unpk(acc[rp*4+1]);
                float2 v2 = unpk(acc[rp*4+2]);
                float2 v3 = unpk(acc[rp*4+3]);
                size_t o0 = ((size_t)b*Fn + t0 + r0) * (Hn*E2n) + (size_t)h*E2n + lane*4;
                *(float4*)&out[o0] =
                    make_float4(v0.x*sc.x, v1.x*sc.x, v2.x*sc.x, v3.x*sc.x);
                *(float4*)&out[o0 + Hn*E2n] =
                    make_float4(v0.y*sc.y, v1.y*sc.y, v2.y*sc.y, v3.y*sc.y);
            }
        }
        __syncthreads();    // bufR free for reuse (tile t+2 probs)
    }
}

// ---------------------------------------------------------------------------

extern "C" void kernel_launch(void* const* d_in, const int* in_sizes, int n_in,
                              void* d_out, int out_size) {
    const float* x   = (const float*)d_in[0];
    const float* adj = (const float*)d_in[1];
    const float* W   = (const float*)d_in[2];
    const float* a   = (const float*)d_in[3];
    float* out = (float*)d_out;

    const int SMEM = (Fn*E2n + 2*BUFSZ + Fn + Fn + 2*64) * 4;   // 213,312 B
    cudaFuncSetAttribute(k_fused, cudaFuncAttributeMaxDynamicSharedMemorySize, SMEM);

    k_fused<<<dim3(Hn, Bn), 512, SMEM>>>(x, adj, W, a, out);    // 1,024 CTAs
}

// round 17
// speedup vs baseline: 1.1145x; 1.1145x over previous
#include <cuda_runtime.h>
#include <math.h>

#define Bn 256
#define Fn 200
#define E1n 64
#define E2n 128
#define Hn 4
#define ALPHAc 0.2f
#define NEGc -9000000000000000.0f

#define APW 68                    // prob buffer row width (64 rows + pad)
#define BUFSZ (Fn*APW)            // 13600 floats per prob buffer

typedef unsigned long long ull;

// ---- packed f32x2 helpers ----
__device__ __forceinline__ ull dup2(float v) {
    ull r; asm("mov.b64 %0, {%1, %1};" : "=l"(r) : "f"(v)); return r;
}
__device__ __forceinline__ void fma2(ull &d, ull a, ull b) {
    asm("fma.rn.f32x2 %0, %1, %2, %0;" : "+l"(d) : "l"(a), "l"(b));
}
__device__ __forceinline__ void add2(ull &d, ull a) {
    asm("add.rn.f32x2 %0, %0, %1;" : "+l"(d) : "l"(a));
}
__device__ __forceinline__ float2 unpk(ull v) {
    float2 r; asm("mov.b64 {%0, %1}, %2;" : "=f"(r.x), "=f"(r.y) : "l"(v)); return r;
}
__device__ __forceinline__ ull d2l(double d) { return __double_as_longlong(d); }

// row-pair-packed step: acc[rp*4+c] = (out[2rp], out[2rp+1]) at col c.
// PA = prob pairs (0,1),(2,3); PB = (4,5),(6,7); HV = 4 h cols. 4 dups + 16 fma2.
#define STEP8(PA, PB, HV)                                                  \
    {                                                                      \
        ull pa0 = d2l(PA.x), pa1 = d2l(PA.y), pb0 = d2l(PB.x), pb1 = d2l(PB.y); \
        ull q;                                                             \
        q = dup2(HV.x); fma2(acc[0], pa0, q); fma2(acc[4], pa1, q); fma2(acc[8],  pb0, q); fma2(acc[12], pb1, q); \
        q = dup2(HV.y); fma2(acc[1], pa0, q); fma2(acc[5], pa1, q); fma2(acc[9],  pb0, q); fma2(acc[13], pb1, q); \
        q = dup2(HV.z); fma2(acc[2], pa0, q); fma2(acc[6], pa1, q); fma2(acc[10], pb0, q); fma2(acc[14], pb1, q); \
        q = dup2(HV.w); fma2(acc[3], pa0, q); fma2(acc[7], pa1, q); fma2(acc[11], pb0, q); fma2(acc[15], pb1, q); \
    }

// ---------------------------------------------------------------------------
// Fused GAT kernel, CTA per (h, b).
// Attention: two 256-thread groups alternate roles per 64-row tile:
//   group (t&1) GEMMs tile t (full y=200) while the other scores tile t+1.
// ---------------------------------------------------------------------------
__global__ __launch_bounds__(512) void k_fused(const float* __restrict__ x,
                                               const float* __restrict__ adj,
                                               const float* __restrict__ W,
                                               const float* __restrict__ a,
                                               float* __restrict__ out) {
    extern __shared__ float smem[];
    float* hs   = smem;                     // 25600
    float* bufs = smem + Fn*E2n;            // 2 * 13600
    float* sjs  = bufs + 2*BUFSZ;           // 200
    float* sis  = sjs + Fn;                 // 200
    float* rsc  = sis + Fn;                 // 2 * 64
    float* xs   = bufs;                     // alias (proj only)
    float* ws   = bufs + 13000;             // alias (proj only)

    int h = blockIdx.x, b = blockIdx.y;
    int tid = threadIdx.x;
    int warp = tid >> 5, lane = tid & 31;

    // ---- stage xs (padded 65) and ws ----
    const float4* xg = (const float4*)(x + (size_t)b * Fn * E1n);
    for (int i = tid; i < Fn*E1n/4; i += 512) {
        float4 v = xg[i];
        int r = i >> 4, c = (i & 15) << 2;
        float* p = &xs[r*65 + c];
        p[0] = v.x; p[1] = v.y; p[2] = v.z; p[3] = v.w;
    }
    const float4* wg = (const float4*)(W + (size_t)h * E1n * E2n);
    float4* ws4 = (float4*)ws;
    for (int i = tid; i < E1n*E2n/4; i += 512) ws4[i] = wg[i];
    __syncthreads();

    // ---- proj GEMM hs = xs @ ws ----
    {
        int tr = tid >> 4;        // active tr<25
        int tc = tid & 15;
        if (tr < 25) {
            ull acc[32];
            #pragma unroll
            for (int i = 0; i < 32; ++i) acc[i] = 0ull;

            #pragma unroll 2
            for (int k = 0; k < E1n; ++k) {
                double2 w0 = *(const double2*)&ws[k*E2n + tc*4];
                double2 w1 = *(const double2*)&ws[k*E2n + 64 + tc*4];
                ull wv0 = d2l(w0.x), wv1 = d2l(w0.y), wv2 = d2l(w1.x), wv3 = d2l(w1.y);
                ull q;
                #pragma unroll
                for (int r = 0; r < 8; ++r) {
                    q = dup2(xs[(tr*8 + r)*65 + k]);
                    fma2(acc[r*4+0], q, wv0);
                    fma2(acc[r*4+1], q, wv1);
                    fma2(acc[r*4+2], q, wv2);
                    fma2(acc[r*4+3], q, wv3);
                }
            }
            #pragma unroll
            for (int r = 0; r < 8; ++r) {
                float2 v0 = unpk(acc[r*4+0]);
                float2 v1 = unpk(acc[r*4+1]);
                float2 v2 = unpk(acc[r*4+2]);
                float2 v3 = unpk(acc[r*4+3]);
                float* dp = &hs[(size_t)(tr*8 + r)*E2n + tc*4];
                *(float4*)dp        = make_float4(v0.x, v0.y, v1.x, v1.y);
                *(float4*)(dp + 64) = make_float4(v2.x, v2.y, v3.x, v3.y);
            }
        }
    }
    __syncthreads();

    // ---- si/sj (warp per row) ----
    {
        const float* ap = a + (size_t)h * 2 * E2n;
        float4 aiv = *(const float4*)&ap[lane*4];
        float4 ajv = *(const float4*)&ap[E2n + lane*4];
        #pragma unroll 1
        for (int it = 0; it < 13; ++it) {
            int f = it*16 + warp;
            if (f < Fn) {
                float4 hv = *(const float4*)&hs[(size_t)f*E2n + lane*4];
                float pi = hv.x*aiv.x + hv.y*aiv.y + hv.z*aiv.z + hv.w*aiv.w;
                float pj = hv.x*ajv.x + hv.y*ajv.y + hv.z*ajv.z + hv.w*ajv.w;
                #pragma unroll
                for (int o = 16; o > 0; o >>= 1) {
                    pi += __shfl_xor_sync(0xffffffffu, pi, o);
                    pj += __shfl_xor_sync(0xffffffffu, pj, o);
                }
                if (lane == 0) { sis[f] = pi; sjs[f] = pj; }
            }
        }
    }
    __syncthreads();

    int grp = tid >> 8;
    int gw  = warp & 7;           // warp index within group

    // ---- score: probs for rows [st0, st0+svalid) into bufW (one group,
    //      8 warps -> 4 row-pair passes: rt0 = p*16+gw, rt1 = rt0+8) ----
    auto score_tile = [&](float* bufW, float* rscW, int st0, int svalid) {
        #pragma unroll 1
        for (int p = 0; p < 4; ++p) {
            int rt0 = p*16 + gw;
            int rt1 = rt0 + 8;
            bool v0 = rt0 < svalid, v1 = rt1 < svalid;   // warp-uniform
            if (!v0) continue;

            float si0 = sis[st0 + rt0];
            float si1 = v1 ? sis[st0 + rt1] : 0.f;
            const float* r0p = adj + (size_t)(st0 + rt0) * Fn;
            const float* r1p = adj + (size_t)(st0 + rt1) * Fn;

            float s0[7], s1[7];
            #pragma unroll
            for (int j = 0; j < 7; ++j) {
                int y = j*32 + lane;
                if (y < Fn) {
                    float sjv = sjs[y];
                    float m0 = r0p[y];
                    float z0 = si0 + sjv;
                    float e0 = (z0 > 0.f) ? z0 : ALPHAc * z0;
                    s0[j] = e0 * ((m0 > 0.f) ? m0 : NEGc);
                    if (v1) {
                        float m1 = r1p[y];
                        float z1 = si1 + sjv;
                        float e1 = (z1 > 0.f) ? z1 : ALPHAc * z1;
                        s1[j] = e1 * ((m1 > 0.f) ? m1 : NEGc);
                    } else s1[j] = -INFINITY;
                } else { s0[j] = -INFINITY; s1[j] = -INFINITY; }
            }

            float mx0 = s0[0], mx1 = s1[0];
            #pragma unroll
            for (int j = 1; j < 7; ++j) { mx0 = fmaxf(mx0, s0[j]); mx1 = fmaxf(mx1, s1[j]); }
            #pragma unroll
            for (int o = 16; o > 0; o >>= 1) {
                mx0 = fmaxf(mx0, __shfl_xor_sync(0xffffffffu, mx0, o));
                mx1 = fmaxf(mx1, __shfl_xor_sync(0xffffffffu, mx1, o));
            }
            float p0[7], p1[7], sum0 = 0.f, sum1 = 0.f;
            #pragma unroll
            for (int j = 0; j < 7; ++j) {
                p0[j] = __expf(s0[j] - mx0); sum0 += p0[j];
                p1[j] = __expf(s1[j] - mx1); sum1 += p1[j];
            }
            #pragma unroll
            for (int o = 16; o > 0; o >>= 1) {
                sum0 += __shfl_xor_sync(0xffffffffu, sum0, o);
                sum1 += __shfl_xor_sync(0xffffffffu, sum1, o);
            }
            #pragma unroll
            for (int j = 0; j < 7; ++j) {
                int y = j*32 + lane;
                if (y < Fn) {
                    bufW[y*APW + rt0] = p0[j];
                    if (v1) bufW[y*APW + rt1] = p1[j];
                }
            }
            if (lane == 0) {
                rscW[rt0] = 1.f / sum0;
                if (v1) rscW[rt1] = 1.f / sum1;
            }
        }
    };

    // ---- prologue: group A scores tile 0 ----
    if (grp == 0) score_tile(bufs, rsc, 0, 64);
    __syncthreads();

    // ---- full tiles 0..2: group (t&1) GEMMs t; other group scores t+1 ----
    #pragma unroll 1
    for (int t = 0; t < 3; ++t) {
        float* bufR = bufs + (t&1)*BUFSZ;
        float* rscR = rsc + (t&1)*64;

        if (grp == (t&1)) {
            ull acc[16];
            #pragma unroll
            for (int i = 0; i < 16; ++i) acc[i] = 0ull;

            const float* pA = bufR + gw*8;
            const float* pH = hs + lane*4;

            double2 aA0 = *(const double2*)&pA[0];
            double2 aA1 = *(const double2*)&pA[4];
            float4  hA  = *(const float4*)&pH[0];

            // over-reads at y=200 land in in-bounds smem, never consumed
            #pragma unroll 1
            for (int y = 0; y < Fn; y += 2) {
                double2 aB0 = *(const double2*)&pA[(y+1)*APW];
                double2 aB1 = *(const double2*)&pA[(y+1)*APW + 4];
                float4  hB  = *(const float4*)&pH[(y+1)*E2n];
                STEP8(aA0, aA1, hA);
                aA0 = *(const double2*)&pA[(y+2)*APW];
                aA1 = *(const double2*)&pA[(y+2)*APW + 4];
                hA  = *(const float4*)&pH[(y+2)*E2n];
                STEP8(aB0, aB1, hB);
            }

            // epilogue: scale by 1/rowsum, store
            #pragma unroll
            for (int rp = 0; rp < 4; ++rp) {
                int r0 = gw*8 + rp*2;
                float2 sc = *(const float2*)&rscR[r0];
                float2 v0 = unpk(acc[rp*4+0]);
                float2 v1 = unpk(acc[rp*4+1]);
                float2 v2 = unpk(acc[rp*4+2]);
                float2 v3 = unpk(acc[rp*4+3]);
                size_t o0 = ((size_t)b*Fn + t*64 + r0) * (Hn*E2n) + (size_t)h*E2n + lane*4;
                *(float4*)&out[o0] =
                    make_float4(v0.x*sc.x, v1.x*sc.x, v2.x*sc.x, v3.x*sc.x);
                *(float4*)&out[o0 + Hn*E2n] =
                    make_float4(v0.y*sc.y, v1.y*sc.y, v2.y*sc.y, v3.y*sc.y);
            }
        } else {
            // scorer: probs for tile t+1 into the other buffer
            score_tile(bufs + ((t+1)&1)*BUFSZ, rsc + ((t+1)&1)*64,
                       (t+1)*64, (t+1 < 3) ? 64 : 8);
        }
        __syncthreads();
    }

    // ---- tail tile (rows 192..199, 8 rows): group B, 8-way y-split ----
    {
        float* bufR = bufs + BUFSZ;        // buf1 (t=3)
        float* rscR = rsc + 64;
        ull* red = (ull*)bufs;             // buf0 free at this point

        if (grp == 1) {
            ull acc[16];
            #pragma unroll
            for (int i = 0; i < 16; ++i) acc[i] = 0ull;

            const float* pA = bufR;        // rows 0..7
            const float* pH = hs + lane*4;
            int yb = gw * 25;
            #pragma unroll 1
            for (int y = yb; y < yb + 25; ++y) {
                double2 a0 = *(const double2*)&pA[y*APW];
                double2 a1 = *(const double2*)&pA[y*APW + 4];
                float4  hv = *(const float4*)&pH[(size_t)y*E2n];
                STEP8(a0, a1, hv);
            }
            #pragma unroll
            for (int i = 0; i < 16; ++i) red[(gw*16 + i)*32 + lane] = acc[i];
        }
        __syncthreads();

        if (grp == 1) {
            int gt = tid & 255;
            #pragma unroll
            for (int oo = 0; oo < 2; ++oo) {
                int o = gt + oo*256;       // 0..511 output ull index
                int i = o >> 5, l = o & 31;
                ull s = red[i*32 + l];
                #pragma unroll
                for (int w = 1; w < 8; ++w) add2(s, red[(w*16 + i)*32 + l]);
                int rp = i >> 2, c = i & 3;
                float2 v = unpk(s);
                float2 sc = *(const float2*)&rscR[rp*2];
                size_t o0 = ((size_t)b*Fn + 192 + rp*2) * (Hn*E2n) + (size_t)h*E2n + l*4 + c;
                out[o0]            = v.x * sc.x;
                out[o0 + Hn*E2n]   = v.y * sc.y;
            }
        }
    }
}

// ---------------------------------------------------------------------------

extern "C" void kernel_launch(void* const* d_in, const int* in_sizes, int n_in,
                              void* d_out, int out_size) {
    const float* x   = (const float*)d_in[0];
    const float* adj = (const float*)d_in[1];
    const float* W   = (const float*)d_in[2];
    const float* a   = (const float*)d_in[3];
    float* out = (float*)d_out;

    const int SMEM = (Fn*E2n + 2*BUFSZ + Fn + Fn + 2*64) * 4;   // 213,312 B
    cudaFuncSetAttribute(k_fused, cudaFuncAttributeMaxDynamicSharedMemorySize, SMEM);

    k_fused<<<dim3(Hn, Bn), 512, SMEM>>>(x, adj, W, a, out);    // 1,024 CTAs
}